// round 9
// baseline (speedup 1.0000x reference)
#include <cuda_runtime.h>
#include <cstdint>

#define NCB   9
#define DIN   512
#define TLEN  4096
#define BATCH 16
#define KCB   1024
#define DCB   8

#define CODES_N   (BATCH * NCB * TLEN)          // 589824
#define LATENT_N  (BATCH * DIN * TLEN)          // 33554432
#define LOSS_OFF  (CODES_N + LATENT_N)
#define LOSS_DEN  (1.0f / (float)(BATCH * DCB * TLEN))   // exact pow2

#define RPAD   516     // residual row pad (floats)
#define WINPAD 516     // W_in row pad

// ---------------- device scratch (precomputed weights) ----------------
__device__ __align__(16) float g_Win  [NCB * DCB * WINPAD];  // [cb][o][c] padded
__device__ __align__(16) float g_WoutP[NCB * 256 * 16];      // [cb][c2][d] float2-interleaved
__device__ __align__(16) float g_cbnT [NCB * DCB * KCB];     // [cb][d][k]
__device__ __align__(16) float g_cn2  [NCB * KCB];           // [cb][k]

typedef unsigned long long u64;

// ---------------- packed fp32x2 helpers ----------------
__device__ __forceinline__ u64 pk2(float a, float b) {
    u64 r; asm("mov.b64 %0,{%1,%2};" : "=l"(r) : "f"(a), "f"(b)); return r;
}
__device__ __forceinline__ u64 dup2(float a) {
    u64 r; asm("mov.b64 %0,{%1,%1};" : "=l"(r) : "f"(a)); return r;
}
__device__ __forceinline__ void up2(u64 v, float& a, float& b) {
    asm("mov.b64 {%0,%1},%2;" : "=f"(a), "=f"(b) : "l"(v));
}
__device__ __forceinline__ u64 f2(u64 a, u64 b, u64 c) {
    u64 d; asm("fma.rn.f32x2 %0,%1,%2,%3;" : "=l"(d) : "l"(a), "l"(b), "l"(c)); return d;
}
__device__ __forceinline__ u64 a2(u64 a, u64 b) {
    u64 d; asm("add.rn.f32x2 %0,%1,%2;" : "=l"(d) : "l"(a), "l"(b)); return d;
}
__device__ __forceinline__ u64 s2(u64 a, u64 b) {   // a - b (exact IEEE)
    return a2(a, b ^ 0x8000000080000000ULL);
}

// NEON VF4+FMA sum of squares over 8 values:
// p_j = fma(x[j+4], x[j+4], x[j]*x[j]);  ss = (p0+p1)+(p2+p3)
__device__ __forceinline__ float ssq8_neon(const float* x) {
    float p0 = __fmaf_rn(x[4], x[4], __fmul_rn(x[0], x[0]));
    float p1 = __fmaf_rn(x[5], x[5], __fmul_rn(x[1], x[1]));
    float p2 = __fmaf_rn(x[6], x[6], __fmul_rn(x[2], x[2]));
    float p3 = __fmaf_rn(x[7], x[7], __fmul_rn(x[3], x[3]));
    return __fadd_rn(__fadd_rn(p0, p1), __fadd_rn(p2, p3));
}

// ---------------- init ----------------
__global__ void rvq_init(float* out) {
    if (threadIdx.x < 2) out[LOSS_OFF + threadIdx.x] = 0.0f;
}

// ---------------- prep: weight-norm + codebook normalization ----------------
// Reductions follow LLVM/NEON vectorized codegen: VF=4, fma contraction,
// interleaved-part lanewise combine, faddp pairwise horizontal.
__global__ void rvq_prep(const float* __restrict__ in_v, const float* __restrict__ in_g,
                         const float* __restrict__ out_v, const float* __restrict__ out_g,
                         const float* __restrict__ cbs) {
    const int cb  = blockIdx.x;
    const int tid = threadIdx.x;

    // W_in [8,512]: one thread per output row. Norm over 512:
    // VF4 x IC2 fma accumulators (stride 8), b_j = a_j + a_{j+4}, faddp tree.
    if (tid < DCB) {
        const float* v = in_v + (cb * DCB + tid) * DIN;
        float a[8];
        #pragma unroll
        for (int j = 0; j < 8; j++) a[j] = 0.f;
        for (int k = 0; k < DIN / 8; k++) {
            #pragma unroll
            for (int j = 0; j < 8; j++) {
                float x = v[8 * k + j];
                a[j] = __fmaf_rn(x, x, a[j]);
            }
        }
        float b0 = __fadd_rn(a[0], a[4]);
        float b1 = __fadd_rn(a[1], a[5]);
        float b2 = __fadd_rn(a[2], a[6]);
        float b3 = __fadd_rn(a[3], a[7]);
        float ss = __fadd_rn(__fadd_rn(b0, b1), __fadd_rn(b2, b3));
        float nrm = __fsqrt_rn(ss);
        float g   = in_g[cb * DCB + tid];
        float* dst = g_Win + (cb * DCB + tid) * WINPAD;
        for (int c = 0; c < DIN; c++) dst[c] = __fdiv_rn(__fmul_rn(g, v[c]), nrm);
        for (int c = DIN; c < WINPAD; c++) dst[c] = 0.f;
    }
    // W_out [512,8]: thread per row; 8-norm via NEON VF4 pattern; interleaved store.
    for (int i = tid; i < DIN; i += blockDim.x) {
        const float* v = out_v + (cb * DIN + i) * DCB;
        float vv[8];
        #pragma unroll
        for (int d = 0; d < DCB; d++) vv[d] = v[d];
        float nrm = __fsqrt_rn(ssq8_neon(vv));
        float g   = out_g[cb * DIN + i];
        #pragma unroll
        for (int d = 0; d < DCB; d++)
            g_WoutP[cb * 4096 + (i >> 1) * 16 + d * 2 + (i & 1)] =
                __fdiv_rn(__fmul_rn(g, vv[d]), nrm);
    }
    // codebook: cb_n = cb / max(||cb||, eps); both sums via NEON VF4 pattern.
    for (int k = tid; k < KCB; k += blockDim.x) {
        const float* v = cbs + (cb * KCB + k) * DCB;
        float vv[8];
        #pragma unroll
        for (int d = 0; d < DCB; d++) vv[d] = v[d];
        float denom = fmaxf(__fsqrt_rn(ssq8_neon(vv)), 1e-12f);
        float cn[8];
        #pragma unroll
        for (int d = 0; d < DCB; d++) {
            cn[d] = __fdiv_rn(vv[d], denom);
            g_cbnT[cb * (DCB * KCB) + d * KCB + k] = cn[d];
        }
        g_cn2[cb * KCB + k] = ssq8_neon(cn);
    }
}

// ---------------- main fused kernel ----------------
// 256 threads; CTA owns 32 consecutive tokens. Residual in SMEM [32][RPAD].
#define SM_R     0                       // 32*516 = 16512
#define SM_WIN   16512                   // 8*516  = 4128
#define SM_WOUTP 20640                   // 4096
#define SM_BOUT  24736                   // 512
#define SM_BIN   25248                   // 8
#define SM_CN2   25256                   // 1024
#define SM_CBN   26280                   // 8192
#define SM_QSTD  34472                   // 512 (32 tok * 8 * u64)
#define SM_FLOATS 34984

__global__ void __launch_bounds__(256, 1)
rvq_main(const float* __restrict__ z, const float* __restrict__ in_b,
         const float* __restrict__ out_b, const float* __restrict__ cbs,
         float* __restrict__ out) {
    extern __shared__ float sm[];
    float* s_R    = sm + SM_R;
    float* s_Win  = sm + SM_WIN;
    float* s_cn2  = sm + SM_CN2;
    float* s_cbn  = sm + SM_CBN;
    float* s_bin  = sm + SM_BIN;

    const int tid  = threadIdx.x;
    const int lane = tid & 31;
    const int w    = tid >> 5;
    const int tauL = tid >> 3;    // 0..31 local token (phase 1)
    const int oo   = tid & 7;     // output channel (phase 1)

    const int tokCTA = blockIdx.x * 32;
    const int b     = tokCTA >> 12;
    const int tbase = tokCTA & 4095;
    const int tw    = tbase + 4 * w;   // warp's first token t-coord

    // ---- load z into SMEM residual R[tok][c] ----
    {
        const float* zp = z + ((size_t)b << 21) + tbase + lane;
        #pragma unroll 4
        for (int it = 0; it < 64; it++) {
            int c = (tid >> 5) + 8 * it;
            s_R[lane * RPAD + c] = zp[(size_t)c << 12];
        }
    }

    u64 lossA = 0ULL, lossB = 0ULL;

    for (int cb = 0; cb < NCB; cb++) {
        __syncthreads();
        // ---- stage weights -> SMEM ----
        {
            const float4* g1 = (const float4*)(g_Win   + cb * (DCB * WINPAD)); // 1032 f4
            const float4* g2 = (const float4*)(g_WoutP + cb * 4096);           // 1024 f4
            const float4* g3 = (const float4*)(g_cbnT  + cb * (DCB * KCB));    // 2048 f4
            const float4* g4 = (const float4*)(g_cn2   + cb * KCB);            // 256 f4
            float4* d1 = (float4*)(sm + SM_WIN);
            float4* d2 = (float4*)(sm + SM_WOUTP);
            float4* d3 = (float4*)(sm + SM_CBN);
            #pragma unroll
            for (int i = 0; i < 4; i++) d1[tid + 256 * i] = g1[tid + 256 * i];
            if (tid < 8) d1[1024 + tid] = g1[1024 + tid];
            #pragma unroll
            for (int i = 0; i < 4; i++) d2[tid + 256 * i] = g2[tid + 256 * i];
            #pragma unroll
            for (int i = 0; i < 8; i++) d3[tid + 256 * i] = g3[tid + 256 * i];
            ((float4*)(sm + SM_CN2))[tid] = g4[tid];
            if (tid < 128) ((float4*)(sm + SM_BOUT))[tid] =
                ((const float4*)(out_b + cb * DIN))[tid];
            if (tid < DCB) s_bin[tid] = in_b[cb * DCB + tid];
        }
        __syncthreads();

        // ---- phase 1: z_e[tauL][oo] as ONE sequential ascending FMA chain over c ----
        float acc = 0.f;
        {
            const float4* wrow = (const float4*)(s_Win + oo * WINPAD);
            const float4* rrow = (const float4*)(s_R + tauL * RPAD);
            #pragma unroll 16
            for (int c4 = 0; c4 < 128; c4++) {
                float4 wv = wrow[c4];
                float4 rv = rrow[c4];
                acc = __fmaf_rn(wv.x, rv.x, acc);
                acc = __fmaf_rn(wv.y, rv.y, acc);
                acc = __fmaf_rn(wv.z, rv.z, acc);
                acc = __fmaf_rn(wv.w, rv.w, acc);
            }
        }
        const float ze = __fadd_rn(acc, s_bin[oo]);

        // ---- gather packed z_e for this warp's 4 tokens via shuffles ----
        u64 zeA[8], zeB[8];
        #pragma unroll
        for (int o = 0; o < 8; o++) {
            float a0  = __shfl_sync(0xffffffffu, ze, o);
            float a1  = __shfl_sync(0xffffffffu, ze, 8 + o);
            float a2v = __shfl_sync(0xffffffffu, ze, 16 + o);
            float a3  = __shfl_sync(0xffffffffu, ze, 24 + o);
            zeA[o] = pk2(a0, a1);
            zeB[o] = pk2(a2v, a3);
        }

        // ---- normalization (NEON VF4+FMA reduce ordering) ----
        float z0[8], z1[8], z2[8], z3[8];
        #pragma unroll
        for (int o = 0; o < 8; o++) { up2(zeA[o], z0[o], z1[o]); up2(zeB[o], z2[o], z3[o]); }
        float dn0 = fmaxf(__fsqrt_rn(ssq8_neon(z0)), 1e-12f);
        float dn1 = fmaxf(__fsqrt_rn(ssq8_neon(z1)), 1e-12f);
        float dn2 = fmaxf(__fsqrt_rn(ssq8_neon(z2)), 1e-12f);
        float dn3 = fmaxf(__fsqrt_rn(ssq8_neon(z3)), 1e-12f);
        u64 zenA[8], zenB[8];
        float a0v[8], a1v[8], a2w[8], a3v[8];
        #pragma unroll
        for (int o = 0; o < 8; o++) {
            a0v[o] = __fdiv_rn(z0[o], dn0);
            a1v[o] = __fdiv_rn(z1[o], dn1);
            a2w[o] = __fdiv_rn(z2[o], dn2);
            a3v[o] = __fdiv_rn(z3[o], dn3);
            zenA[o] = pk2(a0v[o], a1v[o]);
            zenB[o] = pk2(a2w[o], a3v[o]);
        }
        const u64 seA = pk2(ssq8_neon(a0v), ssq8_neon(a1v));
        const u64 seB = pk2(ssq8_neon(a2w), ssq8_neon(a3v));
        const u64 NEG2 = dup2(-2.0f);

        // ---- phase 2: dist = (s_e - 2*dot) + c_k ; argmin over 1024 ----
        float best0 = 3.4e38f, best1 = 3.4e38f, best2 = 3.4e38f, best3 = 3.4e38f;
        int bi0 = 0, bi1 = 0, bi2 = 0, bi3 = 0;
        #pragma unroll 4
        for (int kk = 0; kk < 32; kk++) {
            int k = (kk << 5) + lane;
            u64 dA = 0ULL, dB = 0ULL;
            #pragma unroll
            for (int d = 0; d < 8; d++) {       // Eigen k=8 sequential ascending FMA
                u64 wc = dup2(s_cbn[d * KCB + k]);
                dA = f2(wc, zenA[d], dA);
                dB = f2(wc, zenB[d], dB);
            }
            u64 c2p = dup2(s_cn2[k]);
            u64 sA = a2(f2(dA, NEG2, seA), c2p);
            u64 sB = a2(f2(dB, NEG2, seB), c2p);
            float s0, s1, sv2, s3;
            up2(sA, s0, s1); up2(sB, sv2, s3);
            if (s0 < best0)  { best0 = s0;  bi0 = k; }
            if (s1 < best1)  { best1 = s1;  bi1 = k; }
            if (sv2 < best2) { best2 = sv2; bi2 = k; }
            if (s3 < best3)  { best3 = s3;  bi3 = k; }
        }
        #pragma unroll
        for (int s = 16; s > 0; s >>= 1) {
            float ov; int oi;
            ov = __shfl_xor_sync(0xffffffffu, best0, s); oi = __shfl_xor_sync(0xffffffffu, bi0, s);
            if (ov < best0 || (ov == best0 && oi < bi0)) { best0 = ov; bi0 = oi; }
            ov = __shfl_xor_sync(0xffffffffu, best1, s); oi = __shfl_xor_sync(0xffffffffu, bi1, s);
            if (ov < best1 || (ov == best1 && oi < bi1)) { best1 = ov; bi1 = oi; }
            ov = __shfl_xor_sync(0xffffffffu, best2, s); oi = __shfl_xor_sync(0xffffffffu, bi2, s);
            if (ov < best2 || (ov == best2 && oi < bi2)) { best2 = ov; bi2 = oi; }
            ov = __shfl_xor_sync(0xffffffffu, best3, s); oi = __shfl_xor_sync(0xffffffffu, bi3, s);
            if (ov < best3 || (ov == best3 && oi < bi3)) { best3 = ov; bi3 = oi; }
        }

        // codes output (float), layout [B][NCB][T]
        {
            float* cOut = out + (((size_t)(b * NCB + cb)) << 12) + tw;
            int myi = (lane == 0) ? bi0 : (lane == 1) ? bi1 : (lane == 2) ? bi2 : bi3;
            if (lane < 4) cOut[lane] = (float)myi;
        }

        // raw codebook rows (warp-uniform) -> losses + straight-through qst
        const float* q0 = cbs + ((size_t)(cb * KCB + bi0) << 3);
        const float* q1 = cbs + ((size_t)(cb * KCB + bi1) << 3);
        const float* q2 = cbs + ((size_t)(cb * KCB + bi2) << 3);
        const float* q3 = cbs + ((size_t)(cb * KCB + bi3) << 3);
        u64* qD = (u64*)(sm + SM_QSTD);
        #pragma unroll
        for (int d = 0; d < 8; d++) {
            u64 zqA = pk2(__ldg(q0 + d), __ldg(q1 + d));
            u64 zqB = pk2(__ldg(q2 + d), __ldg(q3 + d));
            u64 eA = s2(zeA[d], zqA);
            u64 eB = s2(zeB[d], zqB);
            lossA = f2(eA, eA, lossA);
            lossB = f2(eB, eB, lossB);
            u64 qstA = a2(zeA[d], s2(zqA, zeA[d]));   // z_e + (z_q - z_e)
            u64 qstB = a2(zeB[d], s2(zqB, zeB[d]));
            float lA, hA, lB, hB;
            up2(qstA, lA, hA); up2(qstB, lB, hB);
            float val = (lane == 0) ? lA : (lane == 1) ? hA : (lane == 2) ? lB : hB;
            if (lane < 4) qD[(4 * w + lane) * 8 + d] = dup2(val);
        }
        __syncthreads();

        // ---- phase 3: residual -= (W_out @ qst + b_out), channel-pair packed ----
        {
            const int c2 = tid;                         // channels 2c2, 2c2+1
            const u64* WpP = (const u64*)(sm + SM_WOUTP) + c2 * 8;
            u64 Wp[8];
            #pragma unroll
            for (int d = 0; d < 8; d++) Wp[d] = WpP[d];
            const u64 bp = ((const u64*)(sm + SM_BOUT))[c2];
            #pragma unroll 4
            for (int tau = 0; tau < 32; tau++) {
                u64 accP = 0ULL;
                #pragma unroll
                for (int d = 0; d < 8; d++) accP = f2(Wp[d], qD[tau * 8 + d], accP);
                accP = a2(accP, bp);
                u64* rp = (u64*)(s_R + tau * RPAD) + c2;
                *rp = s2(*rp, accP);
            }
        }
    }

    // ---- epilogue: latent = z - residual_final ----
    __syncthreads();
    {
        const float* zp = z + ((size_t)b << 21) + tbase + lane;
        float* lp = out + CODES_N + ((size_t)b << 21) + tbase + lane;
        #pragma unroll 4
        for (int it = 0; it < 64; it++) {
            int c = (tid >> 5) + 8 * it;
            float zv = zp[(size_t)c << 12];
            float rv = s_R[lane * RPAD + c];
            lp[(size_t)c << 12] = __fadd_rn(zv, -rv);
        }
    }
    if (lane == 0) {
        float l0, l1, l2, l3;
        up2(lossA, l0, l1); up2(lossB, l2, l3);
        float wl = __fmul_rn(__fadd_rn(__fadd_rn(l0, l1), __fadd_rn(l2, l3)), LOSS_DEN);
        atomicAdd(out + LOSS_OFF, wl);       // closs
        atomicAdd(out + LOSS_OFF + 1, wl);   // bloss (== closs exactly)
    }
}

extern "C" void kernel_launch(void* const* d_in, const int* in_sizes, int n_in,
                              void* d_out, int out_size) {
    const float* z     = (const float*)d_in[0];
    const float* in_v  = (const float*)d_in[1];
    const float* in_g  = (const float*)d_in[2];
    const float* in_b  = (const float*)d_in[3];
    const float* out_v = (const float*)d_in[4];
    const float* out_g = (const float*)d_in[5];
    const float* out_b = (const float*)d_in[6];
    const float* cbs   = (const float*)d_in[7];
    float* out = (float*)d_out;

    cudaFuncSetAttribute(rvq_main, cudaFuncAttributeMaxDynamicSharedMemorySize,
                         SM_FLOATS * sizeof(float));

    rvq_init<<<1, 32>>>(out);
    rvq_prep<<<NCB, 256>>>(in_v, in_g, out_v, out_g, cbs);
    rvq_main<<<(BATCH * TLEN) / 32, 256, SM_FLOATS * sizeof(float)>>>(z, in_b, out_b, cbs, out);
}

// round 10
// speedup vs baseline: 1.2599x; 1.2599x over previous
#include <cuda_runtime.h>
#include <cstdint>

#define NCB   9
#define DIN   512
#define TLEN  4096
#define BATCH 16
#define KCB   1024
#define DCB   8

#define CODES_N   (BATCH * NCB * TLEN)          // 589824
#define LATENT_N  (BATCH * DIN * TLEN)          // 33554432
#define LOSS_OFF  (CODES_N + LATENT_N)
#define LOSS_DEN  (1.0f / (float)(BATCH * DCB * TLEN))   // exact pow2

#define TOKC 64      // tokens per CTA
#define NP   32      // token pairs per CTA

// ---- smem float offsets (all 16B-aligned) ----
#define F_R2   0         // 32 pairs * 514 u64 = 32896 floats
#define F_WIND 32896     // 8 rows * 514 u64   = 8224
#define F_WOUT 41120     // 512*8 scalar       = 4096
#define F_BOUT 45216     // 512
#define F_BIN  45728     // 8
#define F_CN2  45736     // 1024
#define F_CBN  46760     // 8192
#define F_ZE   54952     // 32 pairs * 8 u64   = 512
#define F_QD   55464     // 32 pairs * 8 u64   = 512
#define F_TOT  55976     // 223904 bytes

// ---------------- device scratch (precomputed weights) ----------------
__device__ __align__(16) float g_WinD [NCB * DCB * 1024];  // [cb][o][c] dup'd u64
__device__ __align__(16) float g_WoutS[NCB * DIN * DCB];   // [cb][c][d] scalar
__device__ __align__(16) float g_cbnT [NCB * DCB * KCB];   // [cb][d][k]
__device__ __align__(16) float g_cn2  [NCB * KCB];         // [cb][k]

typedef unsigned long long u64;

// ---------------- packed fp32x2 helpers ----------------
__device__ __forceinline__ u64 pk2(float a, float b) {
    u64 r; asm("mov.b64 %0,{%1,%2};" : "=l"(r) : "f"(a), "f"(b)); return r;
}
__device__ __forceinline__ u64 dup2(float a) {
    u64 r; asm("mov.b64 %0,{%1,%1};" : "=l"(r) : "f"(a)); return r;
}
__device__ __forceinline__ void up2(u64 v, float& a, float& b) {
    asm("mov.b64 {%0,%1},%2;" : "=f"(a), "=f"(b) : "l"(v));
}
__device__ __forceinline__ u64 f2(u64 a, u64 b, u64 c) {
    u64 d; asm("fma.rn.f32x2 %0,%1,%2,%3;" : "=l"(d) : "l"(a), "l"(b), "l"(c)); return d;
}
__device__ __forceinline__ u64 a2(u64 a, u64 b) {
    u64 d; asm("add.rn.f32x2 %0,%1,%2;" : "=l"(d) : "l"(a), "l"(b)); return d;
}
__device__ __forceinline__ u64 s2(u64 a, u64 b) {   // a - b (exact IEEE)
    return a2(a, b ^ 0x8000000080000000ULL);
}

// NEON VF4+FMA sum of squares over 8 values (reference reduce ordering)
__device__ __forceinline__ float ssq8_neon(const float* x) {
    float p0 = __fmaf_rn(x[4], x[4], __fmul_rn(x[0], x[0]));
    float p1 = __fmaf_rn(x[5], x[5], __fmul_rn(x[1], x[1]));
    float p2 = __fmaf_rn(x[6], x[6], __fmul_rn(x[2], x[2]));
    float p3 = __fmaf_rn(x[7], x[7], __fmul_rn(x[3], x[3]));
    return __fadd_rn(__fadd_rn(p0, p1), __fadd_rn(p2, p3));
}

// ---------------- cp.async helpers ----------------
__device__ __forceinline__ void cpa16(uint32_t dst, const void* src) {
    asm volatile("cp.async.cg.shared.global [%0], [%1], 16;" :: "r"(dst), "l"(src));
}
#define CP_COMMIT() asm volatile("cp.async.commit_group;" ::: "memory")
#define CP_WAIT1()  asm volatile("cp.async.wait_group 1;" ::: "memory")
#define CP_WAIT0()  asm volatile("cp.async.wait_group 0;" ::: "memory")

// ---------------- init ----------------
__global__ void rvq_init(float* out) {
    if (threadIdx.x < 2) out[LOSS_OFF + threadIdx.x] = 0.0f;
}

// ---------------- prep (FP orderings identical to the passing R9 version) --------
__global__ void rvq_prep(const float* __restrict__ in_v, const float* __restrict__ in_g,
                         const float* __restrict__ out_v, const float* __restrict__ out_g,
                         const float* __restrict__ cbs) {
    const int cb  = blockIdx.x;
    const int tid = threadIdx.x;

    // W_in [8,512]: thread per row. Norm over 512: VF4xIC2 FMA accumulators,
    // lanewise combine, faddp pairwise tree (NEON codegen ordering).
    if (tid < DCB) {
        const float* v = in_v + (cb * DCB + tid) * DIN;
        float a[8];
        #pragma unroll
        for (int j = 0; j < 8; j++) a[j] = 0.f;
        for (int k = 0; k < DIN / 8; k++) {
            #pragma unroll
            for (int j = 0; j < 8; j++) {
                float x = v[8 * k + j];
                a[j] = __fmaf_rn(x, x, a[j]);
            }
        }
        float b0 = __fadd_rn(a[0], a[4]);
        float b1 = __fadd_rn(a[1], a[5]);
        float b2 = __fadd_rn(a[2], a[6]);
        float b3 = __fadd_rn(a[3], a[7]);
        float ss = __fadd_rn(__fadd_rn(b0, b1), __fadd_rn(b2, b3));
        float nrm = __fsqrt_rn(ss);
        float g   = in_g[cb * DCB + tid];
        u64* dst = ((u64*)g_WinD) + (cb * DCB + tid) * 512;
        for (int c = 0; c < DIN; c++)
            dst[c] = dup2(__fdiv_rn(__fmul_rn(g, v[c]), nrm));
    }
    // W_out [512,8]: 8-norm via NEON VF4 pattern; scalar [c][d] store.
    for (int i = tid; i < DIN; i += blockDim.x) {
        const float* v = out_v + (cb * DIN + i) * DCB;
        float vv[8];
        #pragma unroll
        for (int d = 0; d < DCB; d++) vv[d] = v[d];
        float nrm = __fsqrt_rn(ssq8_neon(vv));
        float g   = out_g[cb * DIN + i];
        #pragma unroll
        for (int d = 0; d < DCB; d++)
            g_WoutS[cb * 4096 + i * 8 + d] = __fdiv_rn(__fmul_rn(g, vv[d]), nrm);
    }
    // codebook: cb_n = cb / max(||cb||, eps); sums via NEON VF4 pattern.
    for (int k = tid; k < KCB; k += blockDim.x) {
        const float* v = cbs + (cb * KCB + k) * DCB;
        float vv[8];
        #pragma unroll
        for (int d = 0; d < DCB; d++) vv[d] = v[d];
        float denom = fmaxf(__fsqrt_rn(ssq8_neon(vv)), 1e-12f);
        float cn[8];
        #pragma unroll
        for (int d = 0; d < DCB; d++) {
            cn[d] = __fdiv_rn(vv[d], denom);
            g_cbnT[cb * (DCB * KCB) + d * KCB + k] = cn[d];
        }
        g_cn2[cb * KCB + k] = ssq8_neon(cn);
    }
}

// ---------------- main fused kernel ----------------
// 256 threads; CTA owns 64 consecutive tokens as 32 interleaved pairs.
__global__ void __launch_bounds__(256, 1)
rvq_main(const float* __restrict__ z, const float* __restrict__ in_b,
         const float* __restrict__ out_b, const float* __restrict__ cbs,
         float* __restrict__ out) {
    extern __shared__ float smF[];
    u64* smU = (u64*)smF;
    uint32_t smB;
    asm("{.reg .u64 t; cvta.to.shared.u64 t, %1; cvt.u32.u64 %0, t;}"
        : "=r"(smB) : "l"(smF));

    const int tid  = threadIdx.x;
    const int lane = tid & 31;
    const int w    = tid >> 5;

    const int tokCTA = blockIdx.x * TOKC;
    const int b     = tokCTA >> 12;
    const int tbase = tokCTA & 4095;

    // ---- load z into R2[p][c] = (z[2p][c], z[2p+1][c]) ----
    {
        const int p = tid & 31, c0 = tid >> 5;
        const float* zp = z + ((size_t)b << 21) + tbase + 2 * p;
        u64* rb = smU + (size_t)p * 514;
        #pragma unroll 4
        for (int it = 0; it < 64; it++) {
            int c = c0 + 8 * it;
            float2 v = *(const float2*)(zp + ((size_t)c << 12));
            rb[c] = pk2(v.x, v.y);
        }
    }

    u64 lossG[4] = {0ULL, 0ULL, 0ULL, 0ULL};

    for (int cb = 0; cb < NCB; cb++) {
        __syncthreads();
        // ---- stage weights via cp.async: group1 = WIND+BIN, group2 = rest ----
        {
            const float* s0 = g_WinD + cb * 8192;
            #pragma unroll
            for (int jj = 0; jj < 8; jj++) {
                int i = tid + 256 * jj;                  // 0..2047
                int row = i >> 8, k4 = i & 255;
                cpa16(smB + (uint32_t)(F_WIND + row * 1028 + k4 * 4) * 4u,
                      s0 + row * 1024 + k4 * 4);
            }
            if (tid < 2) cpa16(smB + (uint32_t)(F_BIN + tid * 4) * 4u,
                               in_b + cb * DCB + tid * 4);
            CP_COMMIT();

            const float* s1 = g_cbnT + cb * (DCB * KCB);
            #pragma unroll
            for (int jj = 0; jj < 8; jj++) {
                int i = tid + 256 * jj;
                cpa16(smB + (uint32_t)(F_CBN + i * 4) * 4u, s1 + i * 4);
            }
            const float* s2p = g_WoutS + cb * 4096;
            #pragma unroll
            for (int jj = 0; jj < 4; jj++) {
                int i = tid + 256 * jj;
                cpa16(smB + (uint32_t)(F_WOUT + i * 4) * 4u, s2p + i * 4);
            }
            cpa16(smB + (uint32_t)(F_CN2 + tid * 4) * 4u, g_cn2 + cb * KCB + tid * 4);
            if (tid < 128) cpa16(smB + (uint32_t)(F_BOUT + tid * 4) * 4u,
                                 out_b + cb * DIN + tid * 4);
            CP_COMMIT();
        }
        CP_WAIT1();
        __syncthreads();

        // ---- phase 1: packed token-pair chain, sequential ascending c ----
        {
            const int p = tid >> 3, oo = tid & 7;
            const u64* wr = smU + (F_WIND / 2) + oo * 514;
            const u64* rr = smU + p * 514;
            u64 acc2 = 0ULL;
            #pragma unroll 8
            for (int c2 = 0; c2 < 256; c2++) {
                ulonglong2 wv = *(const ulonglong2*)(wr + 2 * c2);
                ulonglong2 rv = *(const ulonglong2*)(rr + 2 * c2);
                acc2 = f2(wv.x, rv.x, acc2);
                acc2 = f2(wv.y, rv.y, acc2);
            }
            u64 ze2 = a2(acc2, dup2(smF[F_BIN + oo]));
            smU[(F_ZE / 2) + p * 8 + oo] = ze2;
        }
        CP_WAIT0();
        __syncthreads();

        // ---- per-warp: 8 tokens = pairs 4w..4w+3 ----
        // normalization (NEON ordering per token)
        u64 zen[4][8], seG[4];
        #pragma unroll
        for (int g = 0; g < 4; g++) {
            float lo[8], hi[8];
            #pragma unroll
            for (int o = 0; o < 8; o++)
                up2(smU[(F_ZE / 2) + (4 * w + g) * 8 + o], lo[o], hi[o]);
            float dl = fmaxf(__fsqrt_rn(ssq8_neon(lo)), 1e-12f);
            float dh = fmaxf(__fsqrt_rn(ssq8_neon(hi)), 1e-12f);
            float nl[8], nh[8];
            #pragma unroll
            for (int o = 0; o < 8; o++) {
                nl[o] = __fdiv_rn(lo[o], dl);
                nh[o] = __fdiv_rn(hi[o], dh);
                zen[g][o] = pk2(nl[o], nh[o]);
            }
            seG[g] = pk2(ssq8_neon(nl), ssq8_neon(nh));
        }
        const u64 NEG2 = dup2(-2.0f);

        // ---- phase 2: dist = (s_e - 2*dot) + c_k ; argmin over 1024 ----
        float bestv[8];
        int   besti[8];
        #pragma unroll
        for (int j = 0; j < 8; j++) { bestv[j] = 3.4e38f; besti[j] = 0; }
        #pragma unroll 2
        for (int kk = 0; kk < 32; kk++) {
            int k = (kk << 5) + lane;
            u64 d0 = 0ULL, d1 = 0ULL, d2 = 0ULL, d3 = 0ULL;
            #pragma unroll
            for (int d = 0; d < 8; d++) {       // sequential ascending FMA (Eigen k=8)
                u64 wc = dup2(smF[F_CBN + d * KCB + k]);
                d0 = f2(wc, zen[0][d], d0);
                d1 = f2(wc, zen[1][d], d1);
                d2 = f2(wc, zen[2][d], d2);
                d3 = f2(wc, zen[3][d], d3);
            }
            u64 c2p = dup2(smF[F_CN2 + k]);
            u64 s0 = a2(f2(d0, NEG2, seG[0]), c2p);
            u64 s1 = a2(f2(d1, NEG2, seG[1]), c2p);
            u64 s2v = a2(f2(d2, NEG2, seG[2]), c2p);
            u64 s3 = a2(f2(d3, NEG2, seG[3]), c2p);
            float f[8];
            up2(s0, f[0], f[1]); up2(s1, f[2], f[3]);
            up2(s2v, f[4], f[5]); up2(s3, f[6], f[7]);
            #pragma unroll
            for (int j = 0; j < 8; j++)
                if (f[j] < bestv[j]) { bestv[j] = f[j]; besti[j] = k; }
        }
        // cross-lane argmin, first-index tie-break
        #pragma unroll
        for (int j = 0; j < 8; j++) {
            #pragma unroll
            for (int s = 16; s > 0; s >>= 1) {
                float ov = __shfl_xor_sync(0xffffffffu, bestv[j], s);
                int   oi = __shfl_xor_sync(0xffffffffu, besti[j], s);
                if (ov < bestv[j] || (ov == bestv[j] && oi < besti[j])) {
                    bestv[j] = ov; besti[j] = oi;
                }
            }
        }

        // codes output (float), layout [B][NCB][T]; warp tokens = tbase+8w..+7
        {
            float* cOut = out + (((size_t)(b * NCB + cb)) << 12) + tbase + 8 * w;
            int myi = besti[0];
            if (lane == 1) myi = besti[1];
            if (lane == 2) myi = besti[2];
            if (lane == 3) myi = besti[3];
            if (lane == 4) myi = besti[4];
            if (lane == 5) myi = besti[5];
            if (lane == 6) myi = besti[6];
            if (lane == 7) myi = besti[7];
            if (lane < 8) cOut[lane] = (float)myi;
        }

        // losses + straight-through qst (raw codebook rows, warp-uniform)
        #pragma unroll
        for (int g = 0; g < 4; g++) {
            const float* qlo = cbs + ((size_t)(cb * KCB + besti[2 * g]) << 3);
            const float* qhi = cbs + ((size_t)(cb * KCB + besti[2 * g + 1]) << 3);
            #pragma unroll
            for (int d = 0; d < 8; d++) {
                u64 zq = pk2(__ldg(qlo + d), __ldg(qhi + d));
                u64 ze = smU[(F_ZE / 2) + (4 * w + g) * 8 + d];
                u64 e  = s2(ze, zq);
                lossG[g] = f2(e, e, lossG[g]);
                u64 qst = a2(ze, s2(zq, ze));     // z_e + (z_q - z_e)
                if (lane == g) smU[(F_QD / 2) + (4 * w + g) * 8 + d] = qst;
            }
        }
        __syncthreads();

        // ---- phase 3: residual -= (W_out @ qst + b_out), token-pair packed ----
        {
            const int c1 = tid, c2c = tid + 256;
            u64 W1[8], W2[8];
            #pragma unroll
            for (int d = 0; d < 8; d++) {
                W1[d] = dup2(smF[F_WOUT + c1 * 8 + d]);
                W2[d] = dup2(smF[F_WOUT + c2c * 8 + d]);
            }
            const u64 b1 = dup2(smF[F_BOUT + c1]);
            const u64 b2 = dup2(smF[F_BOUT + c2c]);
            #pragma unroll 2
            for (int p = 0; p < 32; p++) {
                const u64* qd = smU + (F_QD / 2) + p * 8;
                ulonglong2 q01 = *(const ulonglong2*)(qd + 0);
                ulonglong2 q23 = *(const ulonglong2*)(qd + 2);
                ulonglong2 q45 = *(const ulonglong2*)(qd + 4);
                ulonglong2 q67 = *(const ulonglong2*)(qd + 6);
                u64 acc1 = 0ULL, acc2 = 0ULL;
                acc1 = f2(W1[0], q01.x, acc1); acc2 = f2(W2[0], q01.x, acc2);
                acc1 = f2(W1[1], q01.y, acc1); acc2 = f2(W2[1], q01.y, acc2);
                acc1 = f2(W1[2], q23.x, acc1); acc2 = f2(W2[2], q23.x, acc2);
                acc1 = f2(W1[3], q23.y, acc1); acc2 = f2(W2[3], q23.y, acc2);
                acc1 = f2(W1[4], q45.x, acc1); acc2 = f2(W2[4], q45.x, acc2);
                acc1 = f2(W1[5], q45.y, acc1); acc2 = f2(W2[5], q45.y, acc2);
                acc1 = f2(W1[6], q67.x, acc1); acc2 = f2(W2[6], q67.x, acc2);
                acc1 = f2(W1[7], q67.y, acc1); acc2 = f2(W2[7], q67.y, acc2);
                acc1 = a2(acc1, b1);
                acc2 = a2(acc2, b2);
                u64* r1 = smU + p * 514 + c1;
                u64* r2 = smU + p * 514 + c2c;
                *r1 = s2(*r1, acc1);
                *r2 = s2(*r2, acc2);
            }
        }
    }

    // ---- epilogue: latent = z - residual_final ----
    __syncthreads();
    {
        const int p = tid & 31, c0 = tid >> 5;
        const float* zp = z + ((size_t)b << 21) + tbase + 2 * p;
        float* lp = out + CODES_N + ((size_t)b << 21) + tbase + 2 * p;
        const u64* rb = smU + (size_t)p * 514;
        #pragma unroll 4
        for (int it = 0; it < 64; it++) {
            int c = c0 + 8 * it;
            float2 zv = *(const float2*)(zp + ((size_t)c << 12));
            float rl, rh;
            up2(rb[c], rl, rh);
            float2 lv;
            lv.x = __fadd_rn(zv.x, -rl);
            lv.y = __fadd_rn(zv.y, -rh);
            *(float2*)(lp + ((size_t)c << 12)) = lv;
        }
    }
    if (lane == 0) {
        float t0, t1, acc = 0.f;
        #pragma unroll
        for (int g = 0; g < 4; g++) {
            up2(lossG[g], t0, t1);
            acc = __fadd_rn(acc, __fadd_rn(t0, t1));
        }
        float wl = __fmul_rn(acc, LOSS_DEN);
        atomicAdd(out + LOSS_OFF, wl);       // closs
        atomicAdd(out + LOSS_OFF + 1, wl);   // bloss (== closs exactly)
    }
}

extern "C" void kernel_launch(void* const* d_in, const int* in_sizes, int n_in,
                              void* d_out, int out_size) {
    const float* z     = (const float*)d_in[0];
    const float* in_v  = (const float*)d_in[1];
    const float* in_g  = (const float*)d_in[2];
    const float* in_b  = (const float*)d_in[3];
    const float* out_v = (const float*)d_in[4];
    const float* out_g = (const float*)d_in[5];
    const float* out_b = (const float*)d_in[6];
    const float* cbs   = (const float*)d_in[7];
    float* out = (float*)d_out;

    cudaFuncSetAttribute(rvq_main, cudaFuncAttributeMaxDynamicSharedMemorySize,
                         F_TOT * sizeof(float));

    rvq_init<<<1, 32>>>(out);
    rvq_prep<<<NCB, 256>>>(in_v, in_g, out_v, out_g, cbs);
    rvq_main<<<(BATCH * TLEN) / TOKC, 256, F_TOT * sizeof(float)>>>(z, in_b, out_b, cbs, out);
}

// round 11
// speedup vs baseline: 1.3244x; 1.0512x over previous
#include <cuda_runtime.h>
#include <cstdint>

#define NCB   9
#define DIN   512
#define TLEN  4096
#define BATCH 16
#define KCB   1024
#define DCB   8

#define CODES_N   (BATCH * NCB * TLEN)          // 589824
#define LATENT_N  (BATCH * DIN * TLEN)          // 33554432
#define LOSS_OFF  (CODES_N + LATENT_N)
#define LOSS_DEN  (1.0f / (float)(BATCH * DCB * TLEN))   // exact pow2

#define TOKC 64      // tokens per CTA

// ---- smem float offsets (16B-aligned) ----
#define F_R2    0         // 32 pairs * 514 u64 = 32896 floats
#define F_A     32896     // blob A: WIND 8224 + BIN 16 = 8240
#define F_BIN   41120     // = F_A + 8224
#define F_B     41136     // blob B: CBN10 10240 | WOUT 4096 | BOUT 512 = 14848
#define F_WOUTX 51376     // = F_B + 10240
#define F_BOUTX 55472     // = F_B + 14336
#define F_ZE    55984     // 32 pairs * 8 u64 = 512
#define F_QD    56496     // 512
#define F_MB    57008     // 2 mbarriers (u64 each)
#define F_TOT   57016     // 228064 bytes

#define BLOBA_F 8240
#define BLOBB_F 14848
#define BLOBA_BYTES (BLOBA_F * 4)   // 32960
#define BLOBB_BYTES (BLOBB_F * 4)   // 59392

// ---------------- device scratch: per-stage weight blobs (smem-layout-exact) ----
__device__ __align__(16) float g_blobA[NCB * BLOBA_F];
__device__ __align__(16) float g_blobB[NCB * BLOBB_F];

typedef unsigned long long u64;

// ---------------- packed fp32x2 helpers ----------------
__device__ __forceinline__ u64 pk2(float a, float b) {
    u64 r; asm("mov.b64 %0,{%1,%2};" : "=l"(r) : "f"(a), "f"(b)); return r;
}
__device__ __forceinline__ u64 dup2(float a) {
    u64 r; asm("mov.b64 %0,{%1,%1};" : "=l"(r) : "f"(a)); return r;
}
__device__ __forceinline__ void up2(u64 v, float& a, float& b) {
    asm("mov.b64 {%0,%1},%2;" : "=f"(a), "=f"(b) : "l"(v));
}
__device__ __forceinline__ u64 f2(u64 a, u64 b, u64 c) {
    u64 d; asm("fma.rn.f32x2 %0,%1,%2,%3;" : "=l"(d) : "l"(a), "l"(b), "l"(c)); return d;
}
__device__ __forceinline__ u64 a2(u64 a, u64 b) {
    u64 d; asm("add.rn.f32x2 %0,%1,%2;" : "=l"(d) : "l"(a), "l"(b)); return d;
}
__device__ __forceinline__ u64 s2(u64 a, u64 b) {   // a - b (exact IEEE)
    return a2(a, b ^ 0x8000000080000000ULL);
}

// NEON VF4+FMA sum of squares over 8 values (reference reduce ordering)
__device__ __forceinline__ float ssq8_neon(const float* x) {
    float p0 = __fmaf_rn(x[4], x[4], __fmul_rn(x[0], x[0]));
    float p1 = __fmaf_rn(x[5], x[5], __fmul_rn(x[1], x[1]));
    float p2 = __fmaf_rn(x[6], x[6], __fmul_rn(x[2], x[2]));
    float p3 = __fmaf_rn(x[7], x[7], __fmul_rn(x[3], x[3]));
    return __fadd_rn(__fadd_rn(p0, p1), __fadd_rn(p2, p3));
}

// ---------------- mbarrier + bulk copy helpers ----------------
__device__ __forceinline__ void mbar_init(uint32_t mbar, uint32_t cnt) {
    asm volatile("mbarrier.init.shared.b64 [%0], %1;" :: "r"(mbar), "r"(cnt) : "memory");
}
__device__ __forceinline__ void mbar_expect(uint32_t mbar, uint32_t bytes) {
    asm volatile("mbarrier.arrive.expect_tx.shared.b64 _, [%0], %1;"
                 :: "r"(mbar), "r"(bytes) : "memory");
}
__device__ __forceinline__ void mbar_wait(uint32_t mbar, uint32_t parity) {
    asm volatile(
        "{\n\t.reg .pred P;\n"
        "W_%=:\n\t"
        "mbarrier.try_wait.parity.shared.b64 P, [%0], %1;\n\t"
        "@P bra D_%=;\n\t"
        "bra W_%=;\n"
        "D_%=:\n\t}"
        :: "r"(mbar), "r"(parity) : "memory");
}
__device__ __forceinline__ void bulk_cp(uint32_t dst, const void* src,
                                        uint32_t bytes, uint32_t mbar) {
    asm volatile(
        "cp.async.bulk.shared::cluster.global.mbarrier::complete_tx::bytes "
        "[%0], [%1], %2, [%3];"
        :: "r"(dst), "l"(src), "r"(bytes), "r"(mbar) : "memory");
}

// ---------------- init ----------------
__global__ void rvq_init(float* out) {
    if (threadIdx.x < 2) out[LOSS_OFF + threadIdx.x] = 0.0f;
}

// ---------------- prep: bake stage blobs (FP orderings identical to R10) --------
__global__ void rvq_prep(const float* __restrict__ in_v, const float* __restrict__ in_g,
                         const float* __restrict__ in_b,
                         const float* __restrict__ out_v, const float* __restrict__ out_g,
                         const float* __restrict__ out_b,
                         const float* __restrict__ cbs) {
    const int cb  = blockIdx.x;
    const int tid = threadIdx.x;
    float* bA = g_blobA + cb * BLOBA_F;
    float* bB = g_blobB + cb * BLOBB_F;

    // W_in [8,512]: thread per row. Norm over 512: VF4xIC2 FMA accumulators,
    // lanewise combine, faddp pairwise tree (NEON codegen ordering).
    if (tid < DCB) {
        const float* v = in_v + (cb * DCB + tid) * DIN;
        float a[8];
        #pragma unroll
        for (int j = 0; j < 8; j++) a[j] = 0.f;
        for (int k = 0; k < DIN / 8; k++) {
            #pragma unroll
            for (int j = 0; j < 8; j++) {
                float x = v[8 * k + j];
                a[j] = __fmaf_rn(x, x, a[j]);
            }
        }
        float b0 = __fadd_rn(a[0], a[4]);
        float b1 = __fadd_rn(a[1], a[5]);
        float b2 = __fadd_rn(a[2], a[6]);
        float b3 = __fadd_rn(a[3], a[7]);
        float ss = __fadd_rn(__fadd_rn(b0, b1), __fadd_rn(b2, b3));
        float nrm = __fsqrt_rn(ss);
        float g   = in_g[cb * DCB + tid];
        u64* dst = ((u64*)bA) + tid * 514;
        for (int c = 0; c < DIN; c++)
            dst[c] = dup2(__fdiv_rn(__fmul_rn(g, v[c]), nrm));
        dst[512] = 0ULL; dst[513] = 0ULL;
    }
    // BIN (8 values + 8 pad)
    if (tid < 16) bA[8224 + tid] = (tid < 8) ? in_b[cb * DCB + tid] : 0.f;

    // W_out [512,8]: 8-norm via NEON VF4 pattern; scalar [c][d] store into blob B.
    for (int i = tid; i < DIN; i += blockDim.x) {
        const float* v = out_v + (cb * DIN + i) * DCB;
        float vv[8];
        #pragma unroll
        for (int d = 0; d < DCB; d++) vv[d] = v[d];
        float nrm = __fsqrt_rn(ssq8_neon(vv));
        float g   = out_g[cb * DIN + i];
        #pragma unroll
        for (int d = 0; d < DCB; d++)
            bB[10240 + i * 8 + d] = __fdiv_rn(__fmul_rn(g, vv[d]), nrm);
        bB[14336 + i] = out_b[cb * DIN + i];
    }
    // codebook rows: [k][10] = {cb_n[0..7], cn2, 0}; sums via NEON VF4 pattern.
    for (int k = tid; k < KCB; k += blockDim.x) {
        const float* v = cbs + (cb * KCB + k) * DCB;
        float vv[8];
        #pragma unroll
        for (int d = 0; d < DCB; d++) vv[d] = v[d];
        float denom = fmaxf(__fsqrt_rn(ssq8_neon(vv)), 1e-12f);
        float cn[8];
        #pragma unroll
        for (int d = 0; d < DCB; d++) {
            cn[d] = __fdiv_rn(vv[d], denom);
            bB[k * 10 + d] = cn[d];
        }
        bB[k * 10 + 8] = ssq8_neon(cn);
        bB[k * 10 + 9] = 0.f;
    }
}

// ---------------- main fused kernel ----------------
// 256 threads; CTA owns 64 consecutive tokens as 32 interleaved pairs.
__global__ void __launch_bounds__(256, 1)
rvq_main(const float* __restrict__ z, const float* __restrict__ cbs,
         float* __restrict__ out) {
    extern __shared__ float smF[];
    u64* smU = (u64*)smF;
    uint32_t smB;
    asm("{.reg .u64 t; cvta.to.shared.u64 t, %1; cvt.u32.u64 %0, t;}"
        : "=r"(smB) : "l"(smF));
    const uint32_t mbA = smB + F_MB * 4u;
    const uint32_t mbBr = smB + F_MB * 4u + 8u;

    const int tid  = threadIdx.x;
    const int lane = tid & 31;
    const int w    = tid >> 5;

    const int tokCTA = blockIdx.x * TOKC;
    const int b     = tokCTA >> 12;
    const int tbase = tokCTA & 4095;

    if (tid == 0) { mbar_init(mbA, 1); mbar_init(mbBr, 1); }

    // ---- load z into R2[p][c] = (z[2p][c], z[2p+1][c]) ----
    {
        const int p = tid & 31, c0 = tid >> 5;
        const float* zp = z + ((size_t)b << 21) + tbase + 2 * p;
        u64* rb = smU + (size_t)p * 514;
        #pragma unroll 4
        for (int it = 0; it < 64; it++) {
            int c = c0 + 8 * it;
            float2 v = *(const float2*)(zp + ((size_t)c << 12));
            rb[c] = pk2(v.x, v.y);
        }
    }
    __syncthreads();   // mbar init + R2 visible
    if (tid == 0) {    // prefetch A(0)
        mbar_expect(mbA, BLOBA_BYTES);
        bulk_cp(smB + F_A * 4u, g_blobA, BLOBA_BYTES, mbA);
    }

    u64 lossG[4] = {0ULL, 0ULL, 0ULL, 0ULL};

    for (int cb = 0; cb < NCB; cb++) {
        __syncthreads();          // prev phase3 done; B region free
        if (tid == 0) {           // stage B(cb) behind phase 1
            mbar_expect(mbBr, BLOBB_BYTES);
            bulk_cp(smB + F_B * 4u, g_blobB + cb * BLOBB_F, BLOBB_BYTES, mbBr);
        }
        mbar_wait(mbA, cb & 1);   // A(cb) ready

        // ---- phase 1: packed token-pair chain, sequential ascending c ----
        {
            const int p = tid >> 3, oo = tid & 7;
            const u64* wr = smU + (F_A / 2) + oo * 514;
            const u64* rr = smU + p * 514;
            u64 acc2 = 0ULL;
            #pragma unroll 8
            for (int c2 = 0; c2 < 256; c2++) {
                ulonglong2 wv = *(const ulonglong2*)(wr + 2 * c2);
                ulonglong2 rv = *(const ulonglong2*)(rr + 2 * c2);
                acc2 = f2(wv.x, rv.x, acc2);
                acc2 = f2(wv.y, rv.y, acc2);
            }
            u64 ze2 = a2(acc2, dup2(smF[F_BIN + oo]));
            smU[(F_ZE / 2) + p * 8 + oo] = ze2;
        }
        __syncthreads();          // ZE visible; A region free
        if (cb + 1 < NCB && tid == 0) {    // prefetch A(cb+1)
            mbar_expect(mbA, BLOBA_BYTES);
            bulk_cp(smB + F_A * 4u, g_blobA + (cb + 1) * BLOBA_F, BLOBA_BYTES, mbA);
        }
        mbar_wait(mbBr, cb & 1);  // B(cb) ready

        // ---- per-warp: 8 tokens = pairs 4w..4w+3; normalization (NEON order) ----
        u64 zen[4][8], seG[4];
        #pragma unroll
        for (int g = 0; g < 4; g++) {
            float lo[8], hi[8];
            #pragma unroll
            for (int o = 0; o < 8; o++)
                up2(smU[(F_ZE / 2) + (4 * w + g) * 8 + o], lo[o], hi[o]);
            float dl = fmaxf(__fsqrt_rn(ssq8_neon(lo)), 1e-12f);
            float dh = fmaxf(__fsqrt_rn(ssq8_neon(hi)), 1e-12f);
            float nl[8], nh[8];
            #pragma unroll
            for (int o = 0; o < 8; o++) {
                nl[o] = __fdiv_rn(lo[o], dl);
                nh[o] = __fdiv_rn(hi[o], dh);
                zen[g][o] = pk2(nl[o], nh[o]);
            }
            seG[g] = pk2(ssq8_neon(nl), ssq8_neon(nh));
        }
        const u64 NEG2 = dup2(-2.0f);

        // ---- phase 2: dist = (s_e - 2*dot) + c_k ; argmin over 1024 ----
        float bestv[8];
        int   besti[8];
        #pragma unroll
        for (int j = 0; j < 8; j++) { bestv[j] = 3.4e38f; besti[j] = 0; }
        #pragma unroll 2
        for (int kk = 0; kk < 32; kk++) {
            int k = (kk << 5) + lane;
            const float* cbrow = smF + F_B + k * 10;
            float2 c01 = *(const float2*)(cbrow);
            float2 c23 = *(const float2*)(cbrow + 2);
            float2 c45 = *(const float2*)(cbrow + 4);
            float2 c67 = *(const float2*)(cbrow + 6);
            float cw[8] = {c01.x, c01.y, c23.x, c23.y, c45.x, c45.y, c67.x, c67.y};
            float cn2k = cbrow[8];
            u64 d0 = 0ULL, d1 = 0ULL, d2 = 0ULL, d3 = 0ULL;
            #pragma unroll
            for (int d = 0; d < 8; d++) {       // sequential ascending FMA (Eigen k=8)
                u64 wc = dup2(cw[d]);
                d0 = f2(wc, zen[0][d], d0);
                d1 = f2(wc, zen[1][d], d1);
                d2 = f2(wc, zen[2][d], d2);
                d3 = f2(wc, zen[3][d], d3);
            }
            u64 c2p = dup2(cn2k);
            u64 s0 = a2(f2(d0, NEG2, seG[0]), c2p);
            u64 s1 = a2(f2(d1, NEG2, seG[1]), c2p);
            u64 s2v = a2(f2(d2, NEG2, seG[2]), c2p);
            u64 s3 = a2(f2(d3, NEG2, seG[3]), c2p);
            float f[8];
            up2(s0, f[0], f[1]); up2(s1, f[2], f[3]);
            up2(s2v, f[4], f[5]); up2(s3, f[6], f[7]);
            #pragma unroll
            for (int j = 0; j < 8; j++)
                if (f[j] < bestv[j]) { bestv[j] = f[j]; besti[j] = k; }
        }
        // cross-lane argmin, first-index tie-break
        #pragma unroll
        for (int j = 0; j < 8; j++) {
            #pragma unroll
            for (int s = 16; s > 0; s >>= 1) {
                float ov = __shfl_xor_sync(0xffffffffu, bestv[j], s);
                int   oi = __shfl_xor_sync(0xffffffffu, besti[j], s);
                if (ov < bestv[j] || (ov == bestv[j] && oi < besti[j])) {
                    bestv[j] = ov; besti[j] = oi;
                }
            }
        }

        // codes output (float), layout [B][NCB][T]; warp tokens = tbase+8w..+7
        {
            float* cOut = out + (((size_t)(b * NCB + cb)) << 12) + tbase + 8 * w;
            int myi = besti[0];
            if (lane == 1) myi = besti[1];
            if (lane == 2) myi = besti[2];
            if (lane == 3) myi = besti[3];
            if (lane == 4) myi = besti[4];
            if (lane == 5) myi = besti[5];
            if (lane == 6) myi = besti[6];
            if (lane == 7) myi = besti[7];
            if (lane < 8) cOut[lane] = (float)myi;
        }

        // losses + straight-through qst (raw codebook rows, warp-uniform)
        #pragma unroll
        for (int g = 0; g < 4; g++) {
            const float* qlo = cbs + ((size_t)(cb * KCB + besti[2 * g]) << 3);
            const float* qhi = cbs + ((size_t)(cb * KCB + besti[2 * g + 1]) << 3);
            #pragma unroll
            for (int d = 0; d < 8; d++) {
                u64 zq = pk2(__ldg(qlo + d), __ldg(qhi + d));
                u64 ze = smU[(F_ZE / 2) + (4 * w + g) * 8 + d];
                u64 e  = s2(ze, zq);
                lossG[g] = f2(e, e, lossG[g]);
                u64 qst = a2(ze, s2(zq, ze));     // z_e + (z_q - z_e)
                if (lane == g) smU[(F_QD / 2) + (4 * w + g) * 8 + d] = qst;
            }
        }
        __syncthreads();

        // ---- phase 3: residual -= (W_out @ qst + b_out), token-pair packed ----
        {
            const int c1 = tid, c2c = tid + 256;
            u64 W1[8], W2[8];
            #pragma unroll
            for (int d = 0; d < 8; d++) {
                W1[d] = dup2(smF[F_WOUTX + c1 * 8 + d]);
                W2[d] = dup2(smF[F_WOUTX + c2c * 8 + d]);
            }
            const u64 b1 = dup2(smF[F_BOUTX + c1]);
            const u64 b2 = dup2(smF[F_BOUTX + c2c]);
            #pragma unroll 2
            for (int p = 0; p < 32; p++) {
                const u64* qd = smU + (F_QD / 2) + p * 8;
                ulonglong2 q01 = *(const ulonglong2*)(qd + 0);
                ulonglong2 q23 = *(const ulonglong2*)(qd + 2);
                ulonglong2 q45 = *(const ulonglong2*)(qd + 4);
                ulonglong2 q67 = *(const ulonglong2*)(qd + 6);
                u64 acc1 = 0ULL, acc2 = 0ULL;
                acc1 = f2(W1[0], q01.x, acc1); acc2 = f2(W2[0], q01.x, acc2);
                acc1 = f2(W1[1], q01.y, acc1); acc2 = f2(W2[1], q01.y, acc2);
                acc1 = f2(W1[2], q23.x, acc1); acc2 = f2(W2[2], q23.x, acc2);
                acc1 = f2(W1[3], q23.y, acc1); acc2 = f2(W2[3], q23.y, acc2);
                acc1 = f2(W1[4], q45.x, acc1); acc2 = f2(W2[4], q45.x, acc2);
                acc1 = f2(W1[5], q45.y, acc1); acc2 = f2(W2[5], q45.y, acc2);
                acc1 = f2(W1[6], q67.x, acc1); acc2 = f2(W2[6], q67.x, acc2);
                acc1 = f2(W1[7], q67.y, acc1); acc2 = f2(W2[7], q67.y, acc2);
                acc1 = a2(acc1, b1);
                acc2 = a2(acc2, b2);
                u64* r1 = smU + p * 514 + c1;
                u64* r2 = smU + p * 514 + c2c;
                *r1 = s2(*r1, acc1);
                *r2 = s2(*r2, acc2);
            }
        }
    }

    // ---- epilogue: latent = z - residual_final ----
    __syncthreads();
    {
        const int p = tid & 31, c0 = tid >> 5;
        const float* zp = z + ((size_t)b << 21) + tbase + 2 * p;
        float* lp = out + CODES_N + ((size_t)b << 21) + tbase + 2 * p;
        const u64* rb = smU + (size_t)p * 514;
        #pragma unroll 4
        for (int it = 0; it < 64; it++) {
            int c = c0 + 8 * it;
            float2 zv = *(const float2*)(zp + ((size_t)c << 12));
            float rl, rh;
            up2(rb[c], rl, rh);
            float2 lv;
            lv.x = __fadd_rn(zv.x, -rl);
            lv.y = __fadd_rn(zv.y, -rh);
            *(float2*)(lp + ((size_t)c << 12)) = lv;
        }
    }
    if (lane == 0) {
        float t0, t1, acc = 0.f;
        #pragma unroll
        for (int g = 0; g < 4; g++) {
            up2(lossG[g], t0, t1);
            acc = __fadd_rn(acc, __fadd_rn(t0, t1));
        }
        float wl = __fmul_rn(acc, LOSS_DEN);
        atomicAdd(out + LOSS_OFF, wl);       // closs
        atomicAdd(out + LOSS_OFF + 1, wl);   // bloss (== closs exactly)
    }
}

extern "C" void kernel_launch(void* const* d_in, const int* in_sizes, int n_in,
                              void* d_out, int out_size) {
    const float* z     = (const float*)d_in[0];
    const float* in_v  = (const float*)d_in[1];
    const float* in_g  = (const float*)d_in[2];
    const float* in_b  = (const float*)d_in[3];
    const float* out_v = (const float*)d_in[4];
    const float* out_g = (const float*)d_in[5];
    const float* out_b = (const float*)d_in[6];
    const float* cbs   = (const float*)d_in[7];
    float* out = (float*)d_out;

    cudaFuncSetAttribute(rvq_main, cudaFuncAttributeMaxDynamicSharedMemorySize,
                         F_TOT * sizeof(float));

    rvq_init<<<1, 32>>>(out);
    rvq_prep<<<NCB, 256>>>(in_v, in_g, in_b, out_v, out_g, out_b, cbs);
    rvq_main<<<(BATCH * TLEN) / TOKC, 256, F_TOT * sizeof(float)>>>(z, cbs, out);
}

// round 12
// speedup vs baseline: 1.5335x; 1.1579x over previous
#include <cuda_runtime.h>
#include <cstdint>

#define NCB   9
#define DIN   512
#define TLEN  4096
#define BATCH 16
#define KCB   1024
#define DCB   8

#define CODES_N   (BATCH * NCB * TLEN)          // 589824
#define LATENT_N  (BATCH * DIN * TLEN)          // 33554432
#define LOSS_OFF  (CODES_N + LATENT_N)
#define LOSS_DEN  (1.0f / (float)(BATCH * DCB * TLEN))   // exact pow2

#define TOKC 64      // tokens per CTA (32 pairs)

// ---- blob sizes (floats) ----
#define BLOBA_F 4144      // Win scalar [8][516] = 4128 + bin 16
#define BLOBB_F 14848     // CBN [1024][10] 10240 | WOUT_T [8][512] 4096 | BOUT 512
#define BLOBA_BYTES (BLOBA_F * 4)   // 16576
#define BLOBB_BYTES (BLOBB_F * 4)   // 59392

// ---- smem float offsets (16B-aligned) ----
#define F_R2    0         // 32 pairs * 514 u64 = 32896 floats
#define F_A0    32896     // 4144
#define F_A1    37040     // 4144
#define F_B     41184     // 14848
#define F_WOUTT (F_B + 10240)
#define F_BOUTX (F_B + 14336)
#define F_MB    56032     // two u64 mbarriers
#define F_TOT   56048     // 224192 bytes

// ---------------- device scratch: per-stage weight blobs ----------------
__device__ __align__(16) float g_blobA[NCB * BLOBA_F];
__device__ __align__(16) float g_blobB[NCB * BLOBB_F];

typedef unsigned long long u64;

// ---------------- packed fp32x2 helpers ----------------
__device__ __forceinline__ u64 pk2(float a, float b) {
    u64 r; asm("mov.b64 %0,{%1,%2};" : "=l"(r) : "f"(a), "f"(b)); return r;
}
__device__ __forceinline__ u64 dup2(float a) {
    u64 r; asm("mov.b64 %0,{%1,%1};" : "=l"(r) : "f"(a)); return r;
}
__device__ __forceinline__ void up2(u64 v, float& a, float& b) {
    asm("mov.b64 {%0,%1},%2;" : "=f"(a), "=f"(b) : "l"(v));
}
__device__ __forceinline__ u64 f2(u64 a, u64 b, u64 c) {
    u64 d; asm("fma.rn.f32x2 %0,%1,%2,%3;" : "=l"(d) : "l"(a), "l"(b), "l"(c)); return d;
}
__device__ __forceinline__ u64 a2(u64 a, u64 b) {
    u64 d; asm("add.rn.f32x2 %0,%1,%2;" : "=l"(d) : "l"(a), "l"(b)); return d;
}
__device__ __forceinline__ u64 s2(u64 a, u64 b) {   // a - b (exact IEEE)
    return a2(a, b ^ 0x8000000080000000ULL);
}

// NEON VF4+FMA sum of squares over 8 values (reference reduce ordering)
__device__ __forceinline__ float ssq8_neon(const float* x) {
    float p0 = __fmaf_rn(x[4], x[4], __fmul_rn(x[0], x[0]));
    float p1 = __fmaf_rn(x[5], x[5], __fmul_rn(x[1], x[1]));
    float p2 = __fmaf_rn(x[6], x[6], __fmul_rn(x[2], x[2]));
    float p3 = __fmaf_rn(x[7], x[7], __fmul_rn(x[3], x[3]));
    return __fadd_rn(__fadd_rn(p0, p1), __fadd_rn(p2, p3));
}

// ---------------- mbarrier + bulk copy helpers ----------------
__device__ __forceinline__ void mbar_init(uint32_t mbar, uint32_t cnt) {
    asm volatile("mbarrier.init.shared.b64 [%0], %1;" :: "r"(mbar), "r"(cnt) : "memory");
}
__device__ __forceinline__ void mbar_expect(uint32_t mbar, uint32_t bytes) {
    asm volatile("mbarrier.arrive.expect_tx.shared.b64 _, [%0], %1;"
                 :: "r"(mbar), "r"(bytes) : "memory");
}
__device__ __forceinline__ void mbar_wait(uint32_t mbar, uint32_t parity) {
    asm volatile(
        "{\n\t.reg .pred P;\n"
        "W_%=:\n\t"
        "mbarrier.try_wait.parity.shared.b64 P, [%0], %1;\n\t"
        "@P bra D_%=;\n\t"
        "bra W_%=;\n"
        "D_%=:\n\t}"
        :: "r"(mbar), "r"(parity) : "memory");
}
__device__ __forceinline__ void bulk_cp(uint32_t dst, const void* src,
                                        uint32_t bytes, uint32_t mbar) {
    asm volatile(
        "cp.async.bulk.shared::cluster.global.mbarrier::complete_tx::bytes "
        "[%0], [%1], %2, [%3];"
        :: "r"(dst), "l"(src), "r"(bytes), "r"(mbar) : "memory");
}

// ---------------- init ----------------
__global__ void rvq_init(float* out) {
    if (threadIdx.x < 2) out[LOSS_OFF + threadIdx.x] = 0.0f;
}

// ---------------- prep: bake stage blobs (FP orderings identical to R11) --------
__global__ void rvq_prep(const float* __restrict__ in_v, const float* __restrict__ in_g,
                         const float* __restrict__ in_b,
                         const float* __restrict__ out_v, const float* __restrict__ out_g,
                         const float* __restrict__ out_b,
                         const float* __restrict__ cbs) {
    const int cb  = blockIdx.x;
    const int tid = threadIdx.x;
    float* bA = g_blobA + cb * BLOBA_F;
    float* bB = g_blobB + cb * BLOBB_F;

    // W_in [8,512]: thread per row; norm = VF4xIC2 FMA accumulators + faddp tree.
    if (tid < DCB) {
        const float* v = in_v + (cb * DCB + tid) * DIN;
        float a[8];
        #pragma unroll
        for (int j = 0; j < 8; j++) a[j] = 0.f;
        for (int k = 0; k < DIN / 8; k++) {
            #pragma unroll
            for (int j = 0; j < 8; j++) {
                float x = v[8 * k + j];
                a[j] = __fmaf_rn(x, x, a[j]);
            }
        }
        float b0 = __fadd_rn(a[0], a[4]);
        float b1 = __fadd_rn(a[1], a[5]);
        float b2 = __fadd_rn(a[2], a[6]);
        float b3 = __fadd_rn(a[3], a[7]);
        float ss = __fadd_rn(__fadd_rn(b0, b1), __fadd_rn(b2, b3));
        float nrm = __fsqrt_rn(ss);
        float g   = in_g[cb * DCB + tid];
        float* dst = bA + tid * 516;
        for (int c = 0; c < DIN; c++) dst[c] = __fdiv_rn(__fmul_rn(g, v[c]), nrm);
        dst[512] = 0.f; dst[513] = 0.f; dst[514] = 0.f; dst[515] = 0.f;
    }
    if (tid < 16) bA[4128 + tid] = (tid < 8) ? in_b[cb * DCB + tid] : 0.f;

    // W_out [512,8]: 8-norm via NEON VF4; TRANSPOSED store [d][c].
    for (int i = tid; i < DIN; i += blockDim.x) {
        const float* v = out_v + (cb * DIN + i) * DCB;
        float vv[8];
        #pragma unroll
        for (int d = 0; d < DCB; d++) vv[d] = v[d];
        float nrm = __fsqrt_rn(ssq8_neon(vv));
        float g   = out_g[cb * DIN + i];
        #pragma unroll
        for (int d = 0; d < DCB; d++)
            bB[10240 + d * 512 + i] = __fdiv_rn(__fmul_rn(g, vv[d]), nrm);
        bB[14336 + i] = out_b[cb * DIN + i];
    }
    // codebook rows: [k][10] = {cb_n[0..7], cn2, 0}; sums via NEON VF4.
    for (int k = tid; k < KCB; k += blockDim.x) {
        const float* v = cbs + (cb * KCB + k) * DCB;
        float vv[8];
        #pragma unroll
        for (int d = 0; d < DCB; d++) vv[d] = v[d];
        float denom = fmaxf(__fsqrt_rn(ssq8_neon(vv)), 1e-12f);
        float cn[8];
        #pragma unroll
        for (int d = 0; d < DCB; d++) {
            cn[d] = __fdiv_rn(vv[d], denom);
            bB[k * 10 + d] = cn[d];
        }
        bB[k * 10 + 8] = ssq8_neon(cn);
        bB[k * 10 + 9] = 0.f;
    }
}

// ---------------- main fused kernel ----------------
// 256 threads; warp w owns pairs 4w..4w+3 (tokens 8w..8w+7) — warp-independent stages.
__global__ void __launch_bounds__(256, 1)
rvq_main(const float* __restrict__ z, const float* __restrict__ cbs,
         float* __restrict__ out) {
    extern __shared__ float smF[];
    u64* smU = (u64*)smF;
    uint32_t smB;
    asm("{.reg .u64 t; cvta.to.shared.u64 t, %1; cvt.u32.u64 %0, t;}"
        : "=r"(smB) : "l"(smF));
    const uint32_t mbA = smB + F_MB * 4u;
    const uint32_t mbBr = smB + F_MB * 4u + 8u;

    const int tid  = threadIdx.x;
    const int lane = tid & 31;
    const int w    = tid >> 5;

    const int tokCTA = blockIdx.x * TOKC;
    const int b     = tokCTA >> 12;
    const int tbase = tokCTA & 4095;

    if (tid == 0) { mbar_init(mbA, 1); mbar_init(mbBr, 1); }

    // ---- load z into R2[p][c] = (z[2p][c], z[2p+1][c]) ----
    {
        const int p = tid & 31, c0 = tid >> 5;
        const float* zp = z + ((size_t)b << 21) + tbase + 2 * p;
        u64* rb = smU + (size_t)p * 514;
        #pragma unroll 4
        for (int it = 0; it < 64; it++) {
            int c = c0 + 8 * it;
            float2 v = *(const float2*)(zp + ((size_t)c << 12));
            rb[c] = pk2(v.x, v.y);
        }
    }
    __syncthreads();   // mbar init + R2 visible
    if (tid == 0) {    // prefetch A(0) into A0
        mbar_expect(mbA, BLOBA_BYTES);
        bulk_cp(smB + F_A0 * 4u, g_blobA, BLOBA_BYTES, mbA);
    }

    u64 lossG[4] = {0ULL, 0ULL, 0ULL, 0ULL};

    for (int cb = 0; cb < NCB; cb++) {
        // stage top (post-barrier): B(cb) copy, hidden behind phase 1
        if (tid == 0) {
            mbar_expect(mbBr, BLOBB_BYTES);
            bulk_cp(smB + F_B * 4u, g_blobB + cb * BLOBB_F, BLOBB_BYTES, mbBr);
        }
        mbar_wait(mbA, cb & 1);   // A(cb) ready
        if (tid == 0 && cb + 1 < NCB) {   // A(cb+1) into alt buffer, hidden behind stage
            mbar_expect(mbA, BLOBA_BYTES);
            bulk_cp(smB + (uint32_t)((cb & 1) ? F_A0 : F_A1) * 4u,
                    g_blobA + (cb + 1) * BLOBA_F, BLOBA_BYTES, mbA);
        }
        const float* aCur = smF + ((cb & 1) ? F_A1 : F_A0);

        // ---- phase 1 (warp-local): packed token-pair chain, sequential ascending c ----
        u64 ze2;
        {
            const int pl = lane >> 3, oo = lane & 7;
            const float4* wrow = (const float4*)(aCur + oo * 516);
            const u64* rr = smU + (4 * w + pl) * 514;
            u64 acc2 = 0ULL;
            #pragma unroll 8
            for (int c4 = 0; c4 < 128; c4++) {
                float4 wv = wrow[c4];
                ulonglong2 r01 = *(const ulonglong2*)(rr + 4 * c4);
                ulonglong2 r23 = *(const ulonglong2*)(rr + 4 * c4 + 2);
                acc2 = f2(dup2(wv.x), r01.x, acc2);
                acc2 = f2(dup2(wv.y), r01.y, acc2);
                acc2 = f2(dup2(wv.z), r23.x, acc2);
                acc2 = f2(dup2(wv.w), r23.y, acc2);
            }
            ze2 = a2(acc2, dup2(aCur[4128 + oo]));
        }

        // ---- gather ze for this warp's 4 pairs via shuffles (no smem/barrier) ----
        u64 zep[4][8];
        #pragma unroll
        for (int g = 0; g < 4; g++)
            #pragma unroll
            for (int o = 0; o < 8; o++)
                zep[g][o] = __shfl_sync(0xffffffffu, ze2, g * 8 + o);

        // ---- normalization (NEON ordering per token) ----
        u64 zen[4][8], seG[4];
        #pragma unroll
        for (int g = 0; g < 4; g++) {
            float lo[8], hi[8];
            #pragma unroll
            for (int o = 0; o < 8; o++) up2(zep[g][o], lo[o], hi[o]);
            float dl = fmaxf(__fsqrt_rn(ssq8_neon(lo)), 1e-12f);
            float dh = fmaxf(__fsqrt_rn(ssq8_neon(hi)), 1e-12f);
            float nl[8], nh[8];
            #pragma unroll
            for (int o = 0; o < 8; o++) {
                nl[o] = __fdiv_rn(lo[o], dl);
                nh[o] = __fdiv_rn(hi[o], dh);
                zen[g][o] = pk2(nl[o], nh[o]);
            }
            seG[g] = pk2(ssq8_neon(nl), ssq8_neon(nh));
        }
        const u64 NEG2 = dup2(-2.0f);

        mbar_wait(mbBr, cb & 1);  // B(cb) ready

        // ---- phase 2: dist = (s_e - 2*dot) + c_k ; argmin over 1024 ----
        float bestv[8];
        int   besti[8];
        #pragma unroll
        for (int j = 0; j < 8; j++) { bestv[j] = 3.4e38f; besti[j] = 0; }
        #pragma unroll 2
        for (int kk = 0; kk < 32; kk++) {
            int k = (kk << 5) + lane;
            const float* cbrow = smF + F_B + k * 10;
            float2 c01 = *(const float2*)(cbrow);
            float2 c23 = *(const float2*)(cbrow + 2);
            float2 c45 = *(const float2*)(cbrow + 4);
            float2 c67 = *(const float2*)(cbrow + 6);
            float cw[8] = {c01.x, c01.y, c23.x, c23.y, c45.x, c45.y, c67.x, c67.y};
            float cn2k = cbrow[8];
            u64 d0 = 0ULL, d1 = 0ULL, d2 = 0ULL, d3 = 0ULL;
            #pragma unroll
            for (int d = 0; d < 8; d++) {       // sequential ascending FMA (Eigen k=8)
                u64 wc = dup2(cw[d]);
                d0 = f2(wc, zen[0][d], d0);
                d1 = f2(wc, zen[1][d], d1);
                d2 = f2(wc, zen[2][d], d2);
                d3 = f2(wc, zen[3][d], d3);
            }
            u64 c2p = dup2(cn2k);
            u64 s0 = a2(f2(d0, NEG2, seG[0]), c2p);
            u64 s1 = a2(f2(d1, NEG2, seG[1]), c2p);
            u64 s2v = a2(f2(d2, NEG2, seG[2]), c2p);
            u64 s3 = a2(f2(d3, NEG2, seG[3]), c2p);
            float f[8];
            up2(s0, f[0], f[1]); up2(s1, f[2], f[3]);
            up2(s2v, f[4], f[5]); up2(s3, f[6], f[7]);
            #pragma unroll
            for (int j = 0; j < 8; j++)
                if (f[j] < bestv[j]) { bestv[j] = f[j]; besti[j] = k; }
        }
        // cross-lane argmin, first-index tie-break
        #pragma unroll
        for (int j = 0; j < 8; j++) {
            #pragma unroll
            for (int s = 16; s > 0; s >>= 1) {
                float ov = __shfl_xor_sync(0xffffffffu, bestv[j], s);
                int   oi = __shfl_xor_sync(0xffffffffu, besti[j], s);
                if (ov < bestv[j] || (ov == bestv[j] && oi < besti[j])) {
                    bestv[j] = ov; besti[j] = oi;
                }
            }
        }

        // codes output (float), layout [B][NCB][T]; warp tokens = tbase+8w..+7
        {
            float* cOut = out + (((size_t)(b * NCB + cb)) << 12) + tbase + 8 * w;
            int myi = besti[0];
            if (lane == 1) myi = besti[1];
            if (lane == 2) myi = besti[2];
            if (lane == 3) myi = besti[3];
            if (lane == 4) myi = besti[4];
            if (lane == 5) myi = besti[5];
            if (lane == 6) myi = besti[6];
            if (lane == 7) myi = besti[7];
            if (lane < 8) cOut[lane] = (float)myi;
        }

        // losses + straight-through qst (registers; all lanes hold same values)
        u64 qst[4][8];
        #pragma unroll
        for (int g = 0; g < 4; g++) {
            const float* qlo = cbs + ((size_t)(cb * KCB + besti[2 * g]) << 3);
            const float* qhi = cbs + ((size_t)(cb * KCB + besti[2 * g + 1]) << 3);
            #pragma unroll
            for (int d = 0; d < 8; d++) {
                u64 zq = pk2(__ldg(qlo + d), __ldg(qhi + d));
                u64 ze = zep[g][d];
                u64 e  = s2(ze, zq);
                lossG[g] = f2(e, e, lossG[g]);
                qst[g][d] = a2(ze, s2(zq, ze));   // z_e + (z_q - z_e)
            }
        }

        // ---- phase 3 (warp-local): residual[own pairs] -= (W_out @ qst + b_out) ----
        {
            #pragma unroll 2
            for (int c16 = 0; c16 < 16; c16++) {
                const int c = lane + 32 * c16;
                u64 Wd[8];
                #pragma unroll
                for (int d = 0; d < 8; d++)
                    Wd[d] = dup2(smF[F_WOUTT + d * 512 + c]);
                const u64 bc = dup2(smF[F_BOUTX + c]);
                #pragma unroll
                for (int g = 0; g < 4; g++) {
                    u64 acc = 0ULL;
                    #pragma unroll
                    for (int d = 0; d < 8; d++) acc = f2(Wd[d], qst[g][d], acc);
                    acc = a2(acc, bc);
                    u64* rp = smU + (4 * w + g) * 514 + c;
                    *rp = s2(*rp, acc);
                }
            }
        }
        __syncthreads();   // ONE barrier per stage: weight buffers + (final) R2 publish
    }

    // ---- epilogue: latent = z - residual_final ----
    {
        const int p = tid & 31, c0 = tid >> 5;
        const float* zp = z + ((size_t)b << 21) + tbase + 2 * p;
        float* lp = out + CODES_N + ((size_t)b << 21) + tbase + 2 * p;
        const u64* rb = smU + (size_t)p * 514;
        #pragma unroll 4
        for (int it = 0; it < 64; it++) {
            int c = c0 + 8 * it;
            float2 zv = *(const float2*)(zp + ((size_t)c << 12));
            float rl, rh;
            up2(rb[c], rl, rh);
            float2 lv;
            lv.x = __fadd_rn(zv.x, -rl);
            lv.y = __fadd_rn(zv.y, -rh);
            *(float2*)(lp + ((size_t)c << 12)) = lv;
        }
    }
    if (lane == 0) {
        float t0, t1, acc = 0.f;
        #pragma unroll
        for (int g = 0; g < 4; g++) {
            up2(lossG[g], t0, t1);
            acc = __fadd_rn(acc, __fadd_rn(t0, t1));
        }
        float wl = __fmul_rn(acc, LOSS_DEN);
        atomicAdd(out + LOSS_OFF, wl);       // closs
        atomicAdd(out + LOSS_OFF + 1, wl);   // bloss (== closs exactly)
    }
}

extern "C" void kernel_launch(void* const* d_in, const int* in_sizes, int n_in,
                              void* d_out, int out_size) {
    const float* z     = (const float*)d_in[0];
    const float* in_v  = (const float*)d_in[1];
    const float* in_g  = (const float*)d_in[2];
    const float* in_b  = (const float*)d_in[3];
    const float* out_v = (const float*)d_in[4];
    const float* out_g = (const float*)d_in[5];
    const float* out_b = (const float*)d_in[6];
    const float* cbs   = (const float*)d_in[7];
    float* out = (float*)d_out;

    cudaFuncSetAttribute(rvq_main, cudaFuncAttributeMaxDynamicSharedMemorySize,
                         F_TOT * sizeof(float));

    rvq_init<<<1, 32>>>(out);
    rvq_prep<<<NCB, 256>>>(in_v, in_g, in_b, out_v, out_g, out_b, cbs);
    rvq_main<<<(BATCH * TLEN) / TOKC, 256, F_TOT * sizeof(float)>>>(z, cbs, out);
}